// round 14
// baseline (speedup 1.0000x reference)
#include <cuda_runtime.h>
#include <math.h>

#define T_STEPS 1000
#define NS 10
#define NTRAJ 256
#define CHUNKS 100
#define CLEN 10

#define TRAJ_STRIDE (NS*(T_STEPS+1))            /* 10010 floats per trajectory */
#define OUT_TRAJ_SIZE (NTRAJ*TRAJ_STRIDE)       /* 2,562,560 */
#define OUT_PK_OFF   OUT_TRAJ_SIZE
#define OUT_PK_SIZE  (NTRAJ*(T_STEPS+1)*NS*NS)  /* 25,625,600 */
#define OUT_MSE_OFF  (OUT_PK_OFF+OUT_PK_SIZE)   /* 28,188,160 */

// fused_mid launch geometry
#define NB_V  1100     /* chunkv role blocks: 100 chunks x 11 slices          */
#define NB_M  100      /* chunkmat role blocks                                */
#define NB_PK 1200     /* pk role blocks                                      */
#define NB_MID 2400    /* even b -> compute(b/2), odd b -> pk(b/2)            */

// -------- scratch (no allocations allowed) --------
__device__ __align__(16) float d_Amat[T_STEPS*100];   // A_t = (I - K_t H) F  (valid to tconv)
__device__ __align__(16) float d_Kmat[T_STEPS*100];   // K_t                  (valid to tconv)
__device__ __align__(16) float d_Pp  [T_STEPS*100];   // P_pos_t              (valid to tconv)
__device__ int d_tconv;
__device__ __align__(16) float d_Mc  [CHUNKS*100];      // chunk products
__device__ __align__(16) float d_Vc  [CHUNKS*NTRAJ*NS]; // chunk-local affine constants
__device__ __align__(16) float d_Xst [CHUNKS*NTRAJ*NS]; // state at chunk starts
__device__ float d_partial[CHUNKS*NTRAJ];               // per (chunk,traj) sq-error sums

// 10-term dot product with 4 accumulators (short dependency chains)
#define DOT10(EXPR_A, EXPR_B, OUTV)                                            \
    do {                                                                       \
        float a0=0.f,a1=0.f,a2=0.f,a3=0.f;                                     \
        { const int j=0; a0 += (EXPR_A)*(EXPR_B); }                            \
        { const int j=1; a1 += (EXPR_A)*(EXPR_B); }                            \
        { const int j=2; a2 += (EXPR_A)*(EXPR_B); }                            \
        { const int j=3; a3 += (EXPR_A)*(EXPR_B); }                            \
        { const int j=4; a0 += (EXPR_A)*(EXPR_B); }                            \
        { const int j=5; a1 += (EXPR_A)*(EXPR_B); }                            \
        { const int j=6; a2 += (EXPR_A)*(EXPR_B); }                            \
        { const int j=7; a3 += (EXPR_A)*(EXPR_B); }                            \
        { const int j=8; a0 += (EXPR_A)*(EXPR_B); }                            \
        { const int j=9; a1 += (EXPR_A)*(EXPR_B); }                            \
        OUTV = (a0+a1)+(a2+a3);                                                \
    } while (0)

// ============================================================================
// Kernel 1: serial Riccati recursion (single block, runs ALONE — R10 showed
// co-scheduling bulk work with this serial producer costs ~2x; keep isolated).
//   FP = F P ; Pn = FP F^T + Q ; W = FP G + Q H^T  (G = F^T H^T)
//   S = H W + R ; K from in-warp GJ solve S K^T = W^T (fused, no Sinv stage)
//   P_pos = Pn - sym(K W^T) ; A = F - K (H F)
// ============================================================================
__global__ void riccati_kernel(const float* __restrict__ Fg,
                               const float* __restrict__ Hg,
                               const float* __restrict__ Qg,
                               const float* __restrict__ Rg)
{
    __shared__ float Fs[100], Hs[100], HFs[100], Gs[100], QHT[100];
    __shared__ float P[100], FP[100], Pn[100], W[100], Ssh[100], Ks[100];

    const int tid = threadIdx.x;
    const int r = tid / 10, c = tid % 10;
    const bool act = tid < 100;
    float qv = 0.f, rv = 0.f;

    if (act) { Fs[tid] = Fg[tid]; Hs[tid] = Hg[tid]; }
    __syncthreads();
    if (act) {
        qv = Qg[tid]; rv = Rg[tid];
        float s;
        DOT10(Hs[r*10+j], Fs[j*10+c], s);      // HF = H F
        HFs[tid] = s;
        float g;
        DOT10(Fs[j*10+r], Hs[c*10+j], g);      // G[r][c] = sum_k F[k][r] H[c][k]
        Gs[tid] = g;
        float q;
        DOT10(Qg[r*10+j], Hs[c*10+j], q);      // QHT = Q H^T
        QHT[tid] = q;
        P[tid] = (r == c) ? 1.f : 0.f;
    }
    __syncthreads();

    int tconv = T_STEPS - 1;
    for (int t = 0; t < T_STEPS; ++t) {
        // FP = F * P
        if (act) { float s; DOT10(Fs[r*10+j], P[j*10+c], s); FP[tid] = s; }
        __syncthreads();
        // fused: Pn = FP F^T + Q ; W = FP G + QHT
        if (act) {
            float sp, sw;
            DOT10(FP[r*10+j], Fs[c*10+j], sp);
            DOT10(FP[r*10+j], Gs[j*10+c], sw);
            Pn[tid] = sp + qv;
            W[tid]  = sw + QHT[tid];
        }
        __syncthreads();
        // S = H W + R
        if (act) { float s; DOT10(Hs[r*10+j], W[j*10+c], s); Ssh[tid] = s + rv; }
        __syncthreads();
        // in-warp GJ SOLVE: S K^T = W^T  ->  Ks directly (no Sinv, no K stage)
        if (tid < 32) {
            const int lr = (tid < 10) ? tid : 0;
            float sv[10], kv[10];
            #pragma unroll
            for (int j = 0; j < 10; ++j) {
                sv[j] = Ssh[lr*10+j];
                kv[j] = W[j*10+lr];            // row lr of W^T (= column lr of W)
            }
            #pragma unroll
            for (int k = 0; k < 10; ++k) {
                float rk[10], rkv[10];
                #pragma unroll
                for (int j = 0; j < 10; ++j) {
                    rk[j]  = __shfl_sync(0xffffffffu, sv[j], k);
                    rkv[j] = __shfl_sync(0xffffffffu, kv[j], k);
                }
                const float pinv = 1.0f / rk[k];
                if (tid == k) {
                    #pragma unroll
                    for (int j = 0; j < 10; ++j) { sv[j] = rk[j]*pinv; kv[j] = rkv[j]*pinv; }
                } else {
                    const float f = sv[k] * pinv;
                    #pragma unroll
                    for (int j = 0; j < 10; ++j) { sv[j] -= f*rk[j]; kv[j] -= f*rkv[j]; }
                }
            }
            // kv = row lr of S^-1 W^T = (K^T) row lr  =>  K[j][lr] = kv[j]
            if (tid < 10) {
                #pragma unroll
                for (int j = 0; j < 10; ++j) Ks[j*10+lr] = kv[j];
            }
        }
        __syncthreads();
        // fused: Pnew = Pn - sym(K W^T), A = F - K*HF, store, converge
        bool pred = false;
        if (act) {
            float s1, s2, sa;
            DOT10(Ks[r*10+j], W[c*10+j], s1);
            DOT10(W[r*10+j], Ks[c*10+j], s2);
            DOT10(Ks[r*10+j], HFs[j*10+c], sa);
            float pnew = Pn[tid] - 0.5f * (s1 + s2);
            float aval = Fs[tid] - sa;
            pred = fabsf(pnew - P[tid]) > 3e-5f;
            d_Pp  [t*100 + tid] = pnew;
            d_Kmat[t*100 + tid] = Ks[tid];
            d_Amat[t*100 + tid] = aval;
            P[tid] = pnew;
        }
        if (!__syncthreads_or(pred)) { tconv = t; break; }
    }
    if (tid == 0) d_tconv = tconv;
}

// ---------------------------------------------------------------------------
// group-of-10 affine step: lane holds x[row]; matvec via shuffles.
// ---------------------------------------------------------------------------
__device__ __forceinline__ float group_step(const float* __restrict__ Kl,
                                            const float* __restrict__ Al,
                                            float y, float x, int sub, int row)
{
    float sk = 0.f, sa = 0.f;
    #pragma unroll
    for (int j = 0; j < 10; ++j) {
        float yj = __shfl_sync(0xffffffffu, y, sub*10 + j);
        float xj = __shfl_sync(0xffffffffu, x, sub*10 + j);
        sk += Kl[row*10 + j] * yj;
        sa += Al[row*10 + j] * xj;
    }
    return sk + sa;
}

// ============================================================================
// Kernel 2 (fused launch): role-split blocks, interleaved so pk's DRAM stores
// overlap chunkv/chunkmat compute. All roles throughput-bound.
// ============================================================================
__global__ void fused_mid_kernel(const float* __restrict__ Y,
                                 float* __restrict__ out, int out_size)
{
    __shared__ float sA[CLEN*100];
    __shared__ float sK[CLEN*100];
    const int b = blockIdx.x;
    const int tid = threadIdx.x;
    const int tconv = d_tconv;

    if (b & 1) {
        // ------------------- pk role -------------------
        const int pkb = b >> 1;
        long tg = (long)pkb * blockDim.x + tid;
        if (tg < NTRAJ*NS && out_size >= OUT_TRAJ_SIZE) {
            int traj = (int)(tg / NS), i = (int)(tg % NS);
            out[(size_t)traj*TRAJ_STRIDE + i] = 0.f;
        }
        if (out_size < OUT_PK_OFF + 4) return;
        long total4 = (long)OUT_PK_SIZE / 4;
        long lim4 = ((long)out_size - OUT_PK_OFF) / 4;
        if (lim4 < total4) total4 = lim4;
        float4* outp = (float4*)(out + OUT_PK_OFF);
        const long stride = (long)NB_PK * blockDim.x;
        for (long idx = tg; idx < total4; idx += stride) {
            int e4 = (int)(idx % 25);
            long rem = idx / 25;
            int t = (int)(rem % (T_STEPS + 1));
            float4 v;
            if (t == 0) v = make_float4(0.f, 0.f, 0.f, 0.f);
            else {
                int tc = min(t - 1, tconv);
                v = *(const float4*)&d_Pp[tc*100 + e4*4];
            }
            outp[idx] = v;
        }
        return;
    }

    const int idx = b >> 1;
    if (idx < NB_V) {
        // ------------------- chunkv role -------------------
        const int chunk = idx / 11;
        const int slice = idx % 11;
        for (int i = tid; i < CLEN*100; i += blockDim.x) {
            int l = i / 100, e = i % 100;
            int tc = min(chunk*CLEN + l, tconv);
            sA[i] = d_Amat[tc*100 + e];
            sK[i] = d_Kmat[tc*100 + e];
        }
        __syncthreads();

        const int warpId = tid / 32, lane = tid % 32;
        const int sub = lane / 10, row = lane - sub*10;
        const int g = slice*24 + warpId*3 + sub;
        const bool valid = (lane < 30) && (g < NTRAJ);
        const int traj = valid ? g : 0;

        float v = 0.f;
        const float* yb = Y + (size_t)traj * (T_STEPS*NS) + chunk*CLEN*NS;
        #pragma unroll
        for (int l = 0; l < CLEN; ++l) {
            float y = yb[l*10 + row];
            v = group_step(&sK[l*100], &sA[l*100], y, v, sub, row);
        }
        if (valid)
            d_Vc[((size_t)chunk*NTRAJ + traj)*NS + row] = v;
    } else {
        // ------------------- chunkmat role -------------------
        const int chunk = idx - NB_V;
        for (int i = tid; i < CLEN*100; i += blockDim.x) {
            int l = i / 100, e = i % 100;
            int tc = min(chunk*CLEN + l, tconv);
            sA[i] = d_Amat[tc*100 + e];
        }
        __syncthreads();
        float* Mb = sK;   // reuse as Mb[2][100]
        const int r = tid / 10, c = tid % 10;
        const bool act = tid < 100;
        if (act) Mb[tid] = sA[tid];
        __syncthreads();
        for (int l = 1; l < CLEN; ++l) {
            if (act) {
                float s = 0.f;
                #pragma unroll
                for (int j = 0; j < 10; ++j)
                    s += sA[l*100 + r*10+j] * Mb[((l-1)&1)*100 + j*10+c];
                Mb[(l&1)*100 + tid] = s;
            }
            __syncthreads();
        }
        if (act) d_Mc[chunk*100 + tid] = Mb[((CLEN-1)&1)*100 + tid];
    }
}

// ============================================================================
// Kernel 3: serial chain over chunks (shuffle-based, barrier-free loop).
// Runs alone — latency-critical. grid=11, block=256.
// ============================================================================
#define CS_STEP(CH, VREG)                                                      \
    do {                                                                       \
        if (valid) d_Xst[((size_t)(CH)*NTRAJ + traj)*NS + row] = x;            \
        float xn = (VREG);                                                     \
        _Pragma("unroll")                                                      \
        for (int j = 0; j < 10; ++j)                                           \
            xn += Ms[(CH)*100 + row*10 + j] *                                  \
                  __shfl_sync(0xffffffffu, x, sub*10 + j);                     \
        x = xn;                                                                \
    } while (0)

__global__ void chainscan_kernel()
{
    __shared__ float Ms[CHUNKS*100];   // 40 KB
    const int tid = threadIdx.x;
    {
        const float4* src = (const float4*)d_Mc;
        float4* dst = (float4*)Ms;
        for (int i = tid; i < CHUNKS*100/4; i += blockDim.x) dst[i] = src[i];
    }
    __syncthreads();

    const int warpId = tid / 32, lane = tid % 32;
    const int sub = lane / 10, row = lane - sub*10;
    const int traj = (blockIdx.x * (blockDim.x/32) + warpId) * 3 + sub;
    const bool valid = (lane < 30) && (traj < NTRAJ);

    float x = 0.f;
    float vb0, vb1, vb2, vb3;
    #define LDV(CH) ((valid && (CH) < CHUNKS) ? d_Vc[((size_t)(CH)*NTRAJ + traj)*NS + row] : 0.f)
    vb0 = LDV(0); vb1 = LDV(1); vb2 = LDV(2); vb3 = LDV(3);
    for (int ch = 0; ch < CHUNKS; ch += 4) {
        CS_STEP(ch + 0, vb0); vb0 = LDV(ch + 4);
        CS_STEP(ch + 1, vb1); vb1 = LDV(ch + 5);
        CS_STEP(ch + 2, vb2); vb2 = LDV(ch + 6);
        CS_STEP(ch + 3, vb3); vb3 = LDV(ch + 7);
    }
    #undef LDV
}

// ============================================================================
// Kernel 4: replay (group-of-10 lanes). grid=(CHUNKS, 11), block=256.
// ============================================================================
__global__ void replay_kernel(const float* __restrict__ Y,
                              const float* __restrict__ X,
                              float* __restrict__ out, int out_size)
{
    __shared__ float sA[CLEN*100];
    __shared__ float sK[CLEN*100];
    const int chunk = blockIdx.x;
    const int slice = blockIdx.y;
    const int tid = threadIdx.x;
    const int tconv = d_tconv;

    for (int i = tid; i < CLEN*100; i += blockDim.x) {
        int l = i / 100, e = i % 100;
        int tc = min(chunk*CLEN + l, tconv);
        sA[i] = d_Amat[tc*100 + e];
        sK[i] = d_Kmat[tc*100 + e];
    }
    __syncthreads();

    const int warpId = tid / 32, lane = tid % 32;
    const int sub = lane / 10, row = lane - sub*10;
    const int g = slice*24 + warpId*3 + sub;
    const bool valid = (lane < 30) && (g < NTRAJ);
    const int traj = valid ? g : 0;

    float x = d_Xst[((size_t)chunk*NTRAJ + traj)*NS + row];

    const bool wr = valid && (out_size >= OUT_TRAJ_SIZE);
    float errsum = 0.f;
    const float* yb = Y + (size_t)traj * (T_STEPS*NS);
    const float* xb = X + (size_t)traj * TRAJ_STRIDE;
    float* ob = out + (size_t)traj * TRAJ_STRIDE;

    #pragma unroll
    for (int l = 0; l < CLEN; ++l) {
        const int t = chunk*CLEN + l;
        float y = yb[t*10 + row];
        x = group_step(&sK[l*100], &sA[l*100], y, x, sub, row);
        if (wr) ob[(t+1)*10 + row] = x;
        float d = xb[(t+1)*10 + row] - x;
        errsum += d * d;
    }

    float tot = 0.f;
    #pragma unroll
    for (int j = 0; j < 10; ++j)
        tot += __shfl_sync(0xffffffffu, errsum, sub*10 + j);
    if (valid && row == 0)
        d_partial[(size_t)chunk*NTRAJ + traj] = tot;
}

// ============================================================================
// Kernel 5: mse — 1024 threads, 4 lanes per trajectory (25 coalesced loads
// each), shfl reduce within 4-lane group, block tree over 256 dB values.
// ============================================================================
__global__ __launch_bounds__(1024) void mse_kernel(float* __restrict__ out, int out_size)
{
    __shared__ float red[NTRAJ];
    const int tid = threadIdx.x;
    const int traj = tid >> 2;
    const int lane4 = tid & 3;

    float s = 0.f;
    #pragma unroll
    for (int c = 0; c < CHUNKS/4; ++c)
        s += d_partial[(size_t)(c*4 + lane4)*NTRAJ + traj];
    s += __shfl_xor_sync(0xffffffffu, s, 1);
    s += __shfl_xor_sync(0xffffffffu, s, 2);
    if (lane4 == 0)
        red[traj] = 10.f * log10f(s / (float)(T_STEPS * NS));
    __syncthreads();
    for (int off = NTRAJ/2; off > 0; off >>= 1) {
        if (tid < off) red[tid] += red[tid + off];
        __syncthreads();
    }
    if (tid == 0 && OUT_MSE_OFF < out_size)
        out[OUT_MSE_OFF] = red[0] / (float)NTRAJ;
}

// ============================================================================
extern "C" void kernel_launch(void* const* d_in, const int* in_sizes, int n_in,
                              void* d_out, int out_size)
{
    const float* X = (const float*)d_in[0];
    const float* Y = (const float*)d_in[1];
    const float* F = (const float*)d_in[2];
    const float* H = (const float*)d_in[3];
    const float* Q = (const float*)d_in[4];
    const float* R = (const float*)d_in[5];
    float* out = (float*)d_out;

    riccati_kernel  <<<1, 128>>>(F, H, Q, R);
    fused_mid_kernel<<<NB_MID, 256>>>(Y, out, out_size);
    chainscan_kernel<<<11, 256>>>();
    replay_kernel   <<<dim3(CHUNKS, 11), 256>>>(Y, X, out, out_size);
    mse_kernel      <<<1, 1024>>>(out, out_size);
}

// round 15
// speedup vs baseline: 1.0869x; 1.0869x over previous
#include <cuda_runtime.h>
#include <math.h>

#define T_STEPS 1000
#define NS 10
#define NTRAJ 256
#define CHUNKS 100
#define CLEN 10

#define TRAJ_STRIDE (NS*(T_STEPS+1))            /* 10010 floats per trajectory */
#define OUT_TRAJ_SIZE (NTRAJ*TRAJ_STRIDE)       /* 2,562,560 */
#define OUT_PK_OFF   OUT_TRAJ_SIZE
#define OUT_PK_SIZE  (NTRAJ*(T_STEPS+1)*NS*NS)  /* 25,625,600 */
#define OUT_MSE_OFF  (OUT_PK_OFF+OUT_PK_SIZE)   /* 28,188,160 */

// fused_mid launch geometry
#define NB_V  1100     /* chunkv role blocks: 100 chunks x 11 slices          */
#define NB_M  100      /* chunkmat role blocks                                */
#define NB_PK 1200     /* pk role blocks                                      */
#define NB_MID 2400    /* even b -> compute(b/2), odd b -> pk(b/2)            */

// -------- scratch (no allocations allowed) --------
__device__ __align__(16) float d_Amat[T_STEPS*100];   // A_t = (I - K_t H) F
__device__ __align__(16) float d_Kmat[T_STEPS*100];   // K_t
__device__ __align__(16) float d_Pp  [T_STEPS*100];   // P_pos_t
__device__ int d_tconv;
__device__ __align__(16) float d_Mc  [CHUNKS*100];      // chunk products
__device__ __align__(16) float d_Vc  [CHUNKS*NTRAJ*NS]; // chunk-local affine constants
__device__ __align__(16) float d_Xst [CHUNKS*NTRAJ*NS]; // state at chunk starts
__device__ __align__(16) float d_Ky  [T_STEPS*NTRAJ*NS];// K_t * y_t products (from chunkv)
__device__ float d_partial[CHUNKS*NTRAJ];               // per (chunk,traj) sq-error sums

// 10-term dot product with 4 accumulators (short dependency chains)
#define DOT10(EXPR_A, EXPR_B, OUTV)                                            \
    do {                                                                       \
        float a0=0.f,a1=0.f,a2=0.f,a3=0.f;                                     \
        { const int j=0; a0 += (EXPR_A)*(EXPR_B); }                            \
        { const int j=1; a1 += (EXPR_A)*(EXPR_B); }                            \
        { const int j=2; a2 += (EXPR_A)*(EXPR_B); }                            \
        { const int j=3; a3 += (EXPR_A)*(EXPR_B); }                            \
        { const int j=4; a0 += (EXPR_A)*(EXPR_B); }                            \
        { const int j=5; a1 += (EXPR_A)*(EXPR_B); }                            \
        { const int j=6; a2 += (EXPR_A)*(EXPR_B); }                            \
        { const int j=7; a3 += (EXPR_A)*(EXPR_B); }                            \
        { const int j=8; a0 += (EXPR_A)*(EXPR_B); }                            \
        { const int j=9; a1 += (EXPR_A)*(EXPR_B); }                            \
        OUTV = (a0+a1)+(a2+a3);                                                \
    } while (0)

// ============================================================================
// Kernel 1: serial Riccati recursion (single block, runs ALONE — R10 showed
// co-scheduling bulk work with this serial producer costs ~2x).
//   FP = F P ; Pn = FP F^T + Q ; W = FP G + Q H^T  (G = F^T H^T)
//   S = H W + R ; K from in-warp GJ solve S K^T = W^T (fused)
//   P_pos = Pn - sym(K W^T) ; A = F - K (H F)
// ============================================================================
__global__ void riccati_kernel(const float* __restrict__ Fg,
                               const float* __restrict__ Hg,
                               const float* __restrict__ Qg,
                               const float* __restrict__ Rg)
{
    __shared__ float Fs[100], Hs[100], HFs[100], Gs[100], QHT[100];
    __shared__ float P[100], FP[100], Pn[100], W[100], Ssh[100], Ks[100];

    const int tid = threadIdx.x;
    const int r = tid / 10, c = tid % 10;
    const bool act = tid < 100;
    float qv = 0.f, rv = 0.f;

    if (act) { Fs[tid] = Fg[tid]; Hs[tid] = Hg[tid]; }
    __syncthreads();
    if (act) {
        qv = Qg[tid]; rv = Rg[tid];
        float s;
        DOT10(Hs[r*10+j], Fs[j*10+c], s);      // HF = H F
        HFs[tid] = s;
        float g;
        DOT10(Fs[j*10+r], Hs[c*10+j], g);      // G[r][c] = sum_k F[k][r] H[c][k]
        Gs[tid] = g;
        float q;
        DOT10(Qg[r*10+j], Hs[c*10+j], q);      // QHT = Q H^T
        QHT[tid] = q;
        P[tid] = (r == c) ? 1.f : 0.f;
    }
    __syncthreads();

    int tconv = T_STEPS - 1;
    for (int t = 0; t < T_STEPS; ++t) {
        if (act) { float s; DOT10(Fs[r*10+j], P[j*10+c], s); FP[tid] = s; }
        __syncthreads();
        if (act) {
            float sp, sw;
            DOT10(FP[r*10+j], Fs[c*10+j], sp);
            DOT10(FP[r*10+j], Gs[j*10+c], sw);
            Pn[tid] = sp + qv;
            W[tid]  = sw + QHT[tid];
        }
        __syncthreads();
        if (act) { float s; DOT10(Hs[r*10+j], W[j*10+c], s); Ssh[tid] = s + rv; }
        __syncthreads();
        // in-warp GJ SOLVE: S K^T = W^T  ->  Ks directly
        if (tid < 32) {
            const int lr = (tid < 10) ? tid : 0;
            float sv[10], kv[10];
            #pragma unroll
            for (int j = 0; j < 10; ++j) {
                sv[j] = Ssh[lr*10+j];
                kv[j] = W[j*10+lr];
            }
            #pragma unroll
            for (int k = 0; k < 10; ++k) {
                float rk[10], rkv[10];
                #pragma unroll
                for (int j = 0; j < 10; ++j) {
                    rk[j]  = __shfl_sync(0xffffffffu, sv[j], k);
                    rkv[j] = __shfl_sync(0xffffffffu, kv[j], k);
                }
                const float pinv = 1.0f / rk[k];
                if (tid == k) {
                    #pragma unroll
                    for (int j = 0; j < 10; ++j) { sv[j] = rk[j]*pinv; kv[j] = rkv[j]*pinv; }
                } else {
                    const float f = sv[k] * pinv;
                    #pragma unroll
                    for (int j = 0; j < 10; ++j) { sv[j] -= f*rk[j]; kv[j] -= f*rkv[j]; }
                }
            }
            if (tid < 10) {
                #pragma unroll
                for (int j = 0; j < 10; ++j) Ks[j*10+lr] = kv[j];
            }
        }
        __syncthreads();
        bool pred = false;
        if (act) {
            float s1, s2, sa;
            DOT10(Ks[r*10+j], W[c*10+j], s1);
            DOT10(W[r*10+j], Ks[c*10+j], s2);
            DOT10(Ks[r*10+j], HFs[j*10+c], sa);
            float pnew = Pn[tid] - 0.5f * (s1 + s2);
            float aval = Fs[tid] - sa;
            pred = fabsf(pnew - P[tid]) > 3e-5f;
            d_Pp  [t*100 + tid] = pnew;
            d_Kmat[t*100 + tid] = Ks[tid];
            d_Amat[t*100 + tid] = aval;
            P[tid] = pnew;
        }
        if (!__syncthreads_or(pred)) { tconv = t; break; }
    }
    if (tid == 0) d_tconv = tconv;
}

// ============================================================================
// Kernel 2 (fused launch): role-split blocks, interleaved so pk's DRAM stores
// overlap chunkv/chunkmat compute. chunkv additionally emits the per-step
// K_t*y_t products (d_Ky) that replay consumes (bitwise-identical sk values).
// ============================================================================
__global__ void fused_mid_kernel(const float* __restrict__ Y,
                                 float* __restrict__ out, int out_size)
{
    __shared__ float sA[CLEN*100];
    __shared__ float sK[CLEN*100];
    const int b = blockIdx.x;
    const int tid = threadIdx.x;
    const int tconv = d_tconv;

    if (b & 1) {
        // ------------------- pk role -------------------
        const int pkb = b >> 1;
        long tg = (long)pkb * blockDim.x + tid;
        if (tg < NTRAJ*NS && out_size >= OUT_TRAJ_SIZE) {
            int traj = (int)(tg / NS), i = (int)(tg % NS);
            out[(size_t)traj*TRAJ_STRIDE + i] = 0.f;
        }
        if (out_size < OUT_PK_OFF + 4) return;
        long total4 = (long)OUT_PK_SIZE / 4;
        long lim4 = ((long)out_size - OUT_PK_OFF) / 4;
        if (lim4 < total4) total4 = lim4;
        float4* outp = (float4*)(out + OUT_PK_OFF);
        const long stride = (long)NB_PK * blockDim.x;
        for (long idx = tg; idx < total4; idx += stride) {
            int e4 = (int)(idx % 25);
            long rem = idx / 25;
            int t = (int)(rem % (T_STEPS + 1));
            float4 v;
            if (t == 0) v = make_float4(0.f, 0.f, 0.f, 0.f);
            else {
                int tc = min(t - 1, tconv);
                v = *(const float4*)&d_Pp[tc*100 + e4*4];
            }
            __stcs(&outp[idx], v);          // streaming: Pk is never re-read
        }
        return;
    }

    const int idx = b >> 1;
    if (idx < NB_V) {
        // ------------------- chunkv role -------------------
        const int chunk = idx / 11;
        const int slice = idx % 11;
        for (int i = tid; i < CLEN*100; i += blockDim.x) {
            int l = i / 100, e = i % 100;
            int tc = min(chunk*CLEN + l, tconv);
            sA[i] = d_Amat[tc*100 + e];
            sK[i] = d_Kmat[tc*100 + e];
        }
        __syncthreads();

        const int warpId = tid / 32, lane = tid % 32;
        const int sub = lane / 10, row = lane - sub*10;
        const int g = slice*24 + warpId*3 + sub;
        const bool valid = (lane < 30) && (g < NTRAJ);
        const int traj = valid ? g : 0;

        float v = 0.f;
        const float* yb = Y + (size_t)traj * (T_STEPS*NS) + chunk*CLEN*NS;
        #pragma unroll
        for (int l = 0; l < CLEN; ++l) {
            float y = yb[l*10 + row];
            float sk = 0.f, sa = 0.f;
            #pragma unroll
            for (int j = 0; j < 10; ++j) {
                float yj = __shfl_sync(0xffffffffu, y, sub*10 + j);
                sk += sK[l*100 + row*10 + j] * yj;
            }
            #pragma unroll
            for (int j = 0; j < 10; ++j) {
                float xj = __shfl_sync(0xffffffffu, v, sub*10 + j);
                sa += sA[l*100 + row*10 + j] * xj;
            }
            if (valid)
                d_Ky[((size_t)(chunk*CLEN + l)*NTRAJ + traj)*NS + row] = sk;
            v = sk + sa;
        }
        if (valid)
            d_Vc[((size_t)chunk*NTRAJ + traj)*NS + row] = v;
    } else {
        // ------------------- chunkmat role -------------------
        const int chunk = idx - NB_V;
        for (int i = tid; i < CLEN*100; i += blockDim.x) {
            int l = i / 100, e = i % 100;
            int tc = min(chunk*CLEN + l, tconv);
            sA[i] = d_Amat[tc*100 + e];
        }
        __syncthreads();
        float* Mb = sK;   // reuse as Mb[2][100]
        const int r = tid / 10, c = tid % 10;
        const bool act = tid < 100;
        if (act) Mb[tid] = sA[tid];
        __syncthreads();
        for (int l = 1; l < CLEN; ++l) {
            if (act) {
                float s = 0.f;
                #pragma unroll
                for (int j = 0; j < 10; ++j)
                    s += sA[l*100 + r*10+j] * Mb[((l-1)&1)*100 + j*10+c];
                Mb[(l&1)*100 + tid] = s;
            }
            __syncthreads();
        }
        if (act) d_Mc[chunk*100 + tid] = Mb[((CLEN-1)&1)*100 + tid];
    }
}

// ============================================================================
// Kernel 3: serial chain over chunks (shuffle-based, barrier-free loop).
// ============================================================================
#define CS_STEP(CH, VREG)                                                      \
    do {                                                                       \
        if (valid) d_Xst[((size_t)(CH)*NTRAJ + traj)*NS + row] = x;            \
        float xn = (VREG);                                                     \
        _Pragma("unroll")                                                      \
        for (int j = 0; j < 10; ++j)                                           \
            xn += Ms[(CH)*100 + row*10 + j] *                                  \
                  __shfl_sync(0xffffffffu, x, sub*10 + j);                     \
        x = xn;                                                                \
    } while (0)

__global__ void chainscan_kernel()
{
    __shared__ float Ms[CHUNKS*100];   // 40 KB
    const int tid = threadIdx.x;
    {
        const float4* src = (const float4*)d_Mc;
        float4* dst = (float4*)Ms;
        for (int i = tid; i < CHUNKS*100/4; i += blockDim.x) dst[i] = src[i];
    }
    __syncthreads();

    const int warpId = tid / 32, lane = tid % 32;
    const int sub = lane / 10, row = lane - sub*10;
    const int traj = (blockIdx.x * (blockDim.x/32) + warpId) * 3 + sub;
    const bool valid = (lane < 30) && (traj < NTRAJ);

    float x = 0.f;
    float vb0, vb1, vb2, vb3;
    #define LDV(CH) ((valid && (CH) < CHUNKS) ? d_Vc[((size_t)(CH)*NTRAJ + traj)*NS + row] : 0.f)
    vb0 = LDV(0); vb1 = LDV(1); vb2 = LDV(2); vb3 = LDV(3);
    for (int ch = 0; ch < CHUNKS; ch += 4) {
        CS_STEP(ch + 0, vb0); vb0 = LDV(ch + 4);
        CS_STEP(ch + 1, vb1); vb1 = LDV(ch + 5);
        CS_STEP(ch + 2, vb2); vb2 = LDV(ch + 6);
        CS_STEP(ch + 3, vb3); vb3 = LDV(ch + 7);
    }
    #undef LDV
}

// ============================================================================
// Kernel 4: replay (group-of-10 lanes). grid=(CHUNKS, 11), block=256.
// Consumes precomputed K*y (d_Ky): step = 10 LDS + 10 SHFL + 1 global load.
// x evolution bitwise-identical to the previous (sk+sa) formulation.
// ============================================================================
__global__ void replay_kernel(const float* __restrict__ Y,
                              const float* __restrict__ X,
                              float* __restrict__ out, int out_size)
{
    __shared__ float sA[CLEN*100];
    const int chunk = blockIdx.x;
    const int slice = blockIdx.y;
    const int tid = threadIdx.x;
    const int tconv = d_tconv;

    for (int i = tid; i < CLEN*100; i += blockDim.x) {
        int l = i / 100, e = i % 100;
        int tc = min(chunk*CLEN + l, tconv);
        sA[i] = d_Amat[tc*100 + e];
    }
    __syncthreads();

    const int warpId = tid / 32, lane = tid % 32;
    const int sub = lane / 10, row = lane - sub*10;
    const int g = slice*24 + warpId*3 + sub;
    const bool valid = (lane < 30) && (g < NTRAJ);
    const int traj = valid ? g : 0;

    float x = d_Xst[((size_t)chunk*NTRAJ + traj)*NS + row];

    const bool wr = valid && (out_size >= OUT_TRAJ_SIZE);
    float errsum = 0.f;
    const float* xb = X + (size_t)traj * TRAJ_STRIDE;
    float* ob = out + (size_t)traj * TRAJ_STRIDE;

    #pragma unroll
    for (int l = 0; l < CLEN; ++l) {
        const int t = chunk*CLEN + l;
        float ky = d_Ky[((size_t)t*NTRAJ + traj)*NS + row];
        float sa = 0.f;
        #pragma unroll
        for (int j = 0; j < 10; ++j) {
            float xj = __shfl_sync(0xffffffffu, x, sub*10 + j);
            sa += sA[l*100 + row*10 + j] * xj;
        }
        x = ky + sa;
        if (wr) __stcs(&ob[(t+1)*10 + row], x);   // traj out never re-read
        float d = xb[(t+1)*10 + row] - x;
        errsum += d * d;
    }

    float tot = 0.f;
    #pragma unroll
    for (int j = 0; j < 10; ++j)
        tot += __shfl_sync(0xffffffffu, errsum, sub*10 + j);
    if (valid && row == 0)
        d_partial[(size_t)chunk*NTRAJ + traj] = tot;
}

// ============================================================================
// Kernel 5: mse — 1024 threads, 4 lanes per trajectory, shfl + block tree.
// ============================================================================
__global__ __launch_bounds__(1024) void mse_kernel(float* __restrict__ out, int out_size)
{
    __shared__ float red[NTRAJ];
    const int tid = threadIdx.x;
    const int traj = tid >> 2;
    const int lane4 = tid & 3;

    float s = 0.f;
    #pragma unroll
    for (int c = 0; c < CHUNKS/4; ++c)
        s += d_partial[(size_t)(c*4 + lane4)*NTRAJ + traj];
    s += __shfl_xor_sync(0xffffffffu, s, 1);
    s += __shfl_xor_sync(0xffffffffu, s, 2);
    if (lane4 == 0)
        red[traj] = 10.f * log10f(s / (float)(T_STEPS * NS));
    __syncthreads();
    for (int off = NTRAJ/2; off > 0; off >>= 1) {
        if (tid < off) red[tid] += red[tid + off];
        __syncthreads();
    }
    if (tid == 0 && OUT_MSE_OFF < out_size)
        out[OUT_MSE_OFF] = red[0] / (float)NTRAJ;
}

// ============================================================================
extern "C" void kernel_launch(void* const* d_in, const int* in_sizes, int n_in,
                              void* d_out, int out_size)
{
    const float* X = (const float*)d_in[0];
    const float* Y = (const float*)d_in[1];
    const float* F = (const float*)d_in[2];
    const float* H = (const float*)d_in[3];
    const float* Q = (const float*)d_in[4];
    const float* R = (const float*)d_in[5];
    float* out = (float*)d_out;

    riccati_kernel  <<<1, 128>>>(F, H, Q, R);
    fused_mid_kernel<<<NB_MID, 256>>>(Y, out, out_size);
    chainscan_kernel<<<11, 256>>>();
    replay_kernel   <<<dim3(CHUNKS, 11), 256>>>(Y, X, out, out_size);
    mse_kernel      <<<1, 1024>>>(out, out_size);
}